// round 7
// baseline (speedup 1.0000x reference)
#include <cuda_runtime.h>

// HEALPix p=1 padding: x (24,128,128,128) f32 -> y (24,128,130,130) f32
// 2 blocks per plane. Block builds its half of the padded plane in shared
// memory (halo rows/cols included), then streams it to gmem as a contiguous
// 16B-aligned float4 sequence.
//   half 0: output rows 0..63   -> plane floats [0, 8320)
//   half 1: output rows 64..129 -> plane floats [8320, 16900)

#define NN 128
#define NP 130
#define PLANE_IN  (NN*NN)          // 16384
#define PLANE_OUT (NP*NP)          // 16900
#define FACE_DELTA (128*PLANE_IN)  // 2097152
#define NPLANES 3072

// Per-face neighbor table: t, tl, lft, bl, b, br, rgt, tr
__constant__ int NBT[12][8] = {
    {1, 2, 3, 3, 4, 8, 5, 1},      // F0  north
    {2, 3, 0, 0, 5, 9, 6, 2},      // F1
    {3, 0, 1, 1, 6, 10, 7, 3},     // F2
    {0, 1, 2, 2, 7, 11, 4, 0},     // F3
    {0, -1, 3, 7, 11, -1, 8, 5},   // F4  equatorial
    {1, -1, 0, 4, 8, -1, 9, 6},    // F5
    {2, -1, 1, 5, 9, -1, 10, 7},   // F6
    {3, -1, 2, 6, 10, -1, 11, 4},  // F7
    {5, 0, 4, 11, 11, 10, 9, 9},   // F8  south
    {6, 1, 5, 8, 8, 11, 10, 10},   // F9
    {7, 2, 6, 9, 9, 8, 11, 11},    // F10
    {4, 3, 7, 10, 10, 9, 8, 8},    // F11
};

__global__ void __launch_bounds__(256) healpix_pad_kernel(
    const float* __restrict__ x, float* __restrict__ y)
{
    __shared__ float spad[66 * NP];   // 8580 floats = 34320 B

    int bid  = blockIdx.x;
    int P    = bid >> 1;
    int half = bid & 1;
    int tid  = threadIdx.x;
    int warp = tid >> 5;
    int lane = tid & 31;
    int F    = (P >> 7) % 12;
    int ty   = F >> 2;                // 0=north, 1=equatorial, 2=south

    const float* __restrict__ xin = x + (long)P * PLANE_IN;
    float* __restrict__ yout      = y + (long)P * PLANE_OUT;

    int lft_b = (NBT[F][2] - F) * FACE_DELTA;
    int rgt_b = (NBT[F][6] - F) * FACE_DELTA;

    if (half == 0) {
        // ---------- rows 0..63: halo row 0 + interior rows 1..63 (ir 0..62) ----------
        // edge columns straight into smem
        if (tid < 63) {
            int ir = tid;
            spad[(ir + 1) * NP] =
                xin[(ty == 0) ? (lft_b + ir) : (lft_b + ir * NN + (NN - 1))];
        } else if (tid >= 64 && tid < 127) {
            int ir = tid - 64;
            spad[(ir + 1) * NP + 129] =
                xin[(ty == 2) ? (rgt_b + (NN - 1) * NN + ir) : (rgt_b + ir * NN)];
        }

        for (int r = warp; r < 64; r += 8) {
            if (r == 0) {
                // top halo row -> spad[0..129]
                int tbase = (NBT[F][0] - F) * FACE_DELTA;
                for (int j = lane; j < NP; j += 32) {
                    float v;
                    if (j == 0) {
                        if (ty == 0) {
                            v = xin[(NBT[F][1] - F) * FACE_DELTA];              // tl[0,0]
                        } else if (ty == 1) {
                            v = 0.5f * xin[tbase + (NN - 1) * NN]               // t[127,0]
                              + 0.5f * xin[lft_b + (NN - 1)];                   // lft[0,127]
                        } else {
                            v = xin[(NBT[F][1] - F) * FACE_DELTA
                                    + (NN - 1) * NN + (NN - 1)];                // tl[127,127]
                        }
                    } else if (j == NP - 1) {
                        v = xin[(NBT[F][7] - F) * FACE_DELTA + (NN - 1) * NN];  // tr[127,0]
                    } else {
                        int jj = j - 1;
                        v = (ty == 0) ? xin[tbase + jj * NN]                    // t[jj,0]
                                      : xin[tbase + (NN - 1) * NN + jj];        // t[127,jj]
                    }
                    spad[j] = v;
                }
            } else {
                int ir = r - 1;
                float4 f4 = *reinterpret_cast<const float4*>(xin + ir * NN + 4 * lane);
                float* d = spad + r * NP + 1 + 4 * lane;
                d[0] = f4.x; d[1] = f4.y; d[2] = f4.z; d[3] = f4.w;
            }
        }
        __syncthreads();

        // stream out rows 0..63 = plane floats [0, 8320), fully aligned
        for (int i = 4 * tid; i < 64 * NP; i += 4 * 256) {
            *reinterpret_cast<float4*>(yout + i) =
                *reinterpret_cast<const float4*>(spad + i);
        }
    } else {
        // ---------- rows 64..129 (rr = r-64): interior rr 0..64 (ir 63..127) + halo rr 65 ----------
        if (tid < 65) {
            int rr = tid, ir = 63 + tid;
            spad[rr * NP] =
                xin[(ty == 0) ? (lft_b + ir) : (lft_b + ir * NN + (NN - 1))];
        } else if (tid >= 128 && tid < 193) {
            int rr = tid - 128, ir = 63 + rr;
            spad[rr * NP + 129] =
                xin[(ty == 2) ? (rgt_b + (NN - 1) * NN + ir) : (rgt_b + ir * NN)];
        }

        for (int rr = warp; rr < 66; rr += 8) {
            if (rr == 65) {
                // bottom halo row -> spad[65*130 .. +129]
                int bbase = (NBT[F][4] - F) * FACE_DELTA;
                for (int j = lane; j < NP; j += 32) {
                    float v;
                    if (j == 0) {
                        v = xin[(NBT[F][3] - F) * FACE_DELTA + (NN - 1)];       // bl[0,127]
                    } else if (j == NP - 1) {
                        if (ty == 0) {
                            v = xin[(NBT[F][5] - F) * FACE_DELTA];              // br[0,0]
                        } else if (ty == 1) {
                            v = 0.5f * xin[bbase + (NN - 1)]                    // b[0,127]
                              + 0.5f * xin[rgt_b + (NN - 1) * NN];              // rgt[127,0]
                        } else {
                            v = xin[(NBT[F][5] - F) * FACE_DELTA
                                    + (NN - 1) * NN + (NN - 1)];                // br[127,127]
                        }
                    } else {
                        int jj = j - 1;
                        v = (ty == 2) ? xin[bbase + jj * NN + (NN - 1)]         // b[jj,127]
                                      : xin[bbase + jj];                        // b[0,jj]
                    }
                    spad[65 * NP + j] = v;
                }
            } else {
                int ir = 63 + rr;
                float4 f4 = *reinterpret_cast<const float4*>(xin + ir * NN + 4 * lane);
                float* d = spad + rr * NP + 1 + 4 * lane;
                d[0] = f4.x; d[1] = f4.y; d[2] = f4.z; d[3] = f4.w;
            }
        }
        __syncthreads();

        // stream out rows 64..129 = plane floats [8320, 16900), base 16B-aligned
        float* dst = yout + 64 * NP;
        for (int i = 4 * tid; i < 66 * NP; i += 4 * 256) {
            *reinterpret_cast<float4*>(dst + i) =
                *reinterpret_cast<const float4*>(spad + i);
        }
    }
}

extern "C" void kernel_launch(void* const* d_in, const int* in_sizes, int n_in,
                              void* d_out, int out_size)
{
    const float* x = (const float*)d_in[0];
    float* y = (float*)d_out;
    healpix_pad_kernel<<<NPLANES * 2, 256>>>(x, y);
}

// round 8
// speedup vs baseline: 1.2669x; 1.2669x over previous
#include <cuda_runtime.h>

// HEALPix p=1 padding: x (24,128,128,128) f32 -> y (24,128,130,130) f32
// One launch. Blocks [0,768) = halo rows; blocks [768,3840) = interior,
// one plane per block, 8 warps x 16 rows, 4-deep load->store pipeline.

#define NN 128
#define NP 130
#define PLANE_IN  (NN*NN)          // 16384
#define PLANE_OUT (NP*NP)          // 16900
#define FACE_DELTA (128*PLANE_IN)  // 2097152
#define NPLANES 3072
#define HALO_BLOCKS ((NPLANES*2)/8)   // 768
#define TOTAL_BLOCKS (HALO_BLOCKS + NPLANES)

// Per-face neighbor table: t, tl, lft, bl, b, br, rgt, tr
__constant__ int NBT[12][8] = {
    {1, 2, 3, 3, 4, 8, 5, 1},      // F0  north
    {2, 3, 0, 0, 5, 9, 6, 2},      // F1
    {3, 0, 1, 1, 6, 10, 7, 3},     // F2
    {0, 1, 2, 2, 7, 11, 4, 0},     // F3
    {0, -1, 3, 7, 11, -1, 8, 5},   // F4  equatorial
    {1, -1, 0, 4, 8, -1, 9, 6},    // F5
    {2, -1, 1, 5, 9, -1, 10, 7},   // F6
    {3, -1, 2, 6, 10, -1, 11, 4},  // F7
    {5, 0, 4, 11, 11, 10, 9, 9},   // F8  south
    {6, 1, 5, 8, 8, 11, 10, 10},   // F9
    {7, 2, 6, 9, 9, 8, 11, 11},    // F10
    {4, 3, 7, 10, 10, 9, 8, 8},    // F11
};

__device__ __forceinline__ void store_row(
    float* __restrict__ outrow, float4 f4, float lh, float rh, int r, int lane)
{
    if (r & 1) {
        // odd r: aligned 16B chunks at cols [4k+2 .. 4k+5]
        float s = __shfl_down_sync(0xffffffffu, f4.x, 1);   // in[4*lane+4]
        if (lane == 31) s = rh;
        *reinterpret_cast<float4*>(outrow + 4 * lane + 2) =
            make_float4(f4.y, f4.z, f4.w, s);
        if (lane == 0) { outrow[0] = lh; outrow[1] = f4.x; }
    } else {
        // even r: aligned 16B chunks at cols [4k .. 4k+3]
        float s = __shfl_up_sync(0xffffffffu, f4.w, 1);     // in[4*lane-1]
        if (lane == 0) s = lh;
        *reinterpret_cast<float4*>(outrow + 4 * lane) =
            make_float4(s, f4.x, f4.y, f4.z);
        if (lane == 31) { outrow[128] = f4.w; outrow[129] = rh; }
    }
}

__global__ void __launch_bounds__(256) healpix_pad_kernel(
    const float* __restrict__ x, float* __restrict__ y)
{
    if (blockIdx.x >= HALO_BLOCKS) {
        // ================= interior rows: one plane per block =================
        __shared__ float sl[NN];   // left edge value per input row
        __shared__ float sr[NN];   // right edge value per input row

        int P    = blockIdx.x - HALO_BLOCKS;
        int tid  = threadIdx.x;
        int warp = tid >> 5;
        int lane = tid & 31;
        int F    = (P >> 7) % 12;
        int ty   = F >> 2;         // 0=north, 1=equatorial, 2=south

        const float* __restrict__ xin = x + (long)P * PLANE_IN;
        float* __restrict__ yout      = y + (long)P * PLANE_OUT;

        int lft_b = (NBT[F][2] - F) * FACE_DELTA;
        int rgt_b = (NBT[F][6] - F) * FACE_DELTA;

        // stage edge columns: 128 threads each side, all loads in flight
        if (tid < NN) {
            int ir = tid;
            sl[ir] = xin[(ty == 0) ? (lft_b + ir) : (lft_b + ir * NN + (NN - 1))];
        } else {
            int ir = tid - NN;
            sr[ir] = xin[(ty == 2) ? (rgt_b + (NN - 1) * NN + ir) : (rgt_b + ir * NN)];
        }
        __syncthreads();

        int ir0 = warp * 16;
        const float* base = xin + ir0 * NN + 4 * lane;

        // 4-deep register FIFO: load row k+4 before storing row k
        float4 buf[4];
        #pragma unroll
        for (int j = 0; j < 4; ++j)
            buf[j] = *reinterpret_cast<const float4*>(base + j * NN);

        #pragma unroll
        for (int k = 0; k < 16; ++k) {
            float4 cur = buf[k & 3];
            if (k + 4 < 16)
                buf[k & 3] = *reinterpret_cast<const float4*>(base + (k + 4) * NN);
            int ir = ir0 + k;
            int r  = ir + 1;
            store_row(yout + r * NP, cur, sl[ir], sr[ir], r, lane);
        }
    } else {
        // ================= halo rows: 1 warp per row (runs first) =================
        int hb   = blockIdx.x;
        int warp = threadIdx.x >> 5;
        int lane = threadIdx.x & 31;
        int w    = hb * 8 + warp;              // 0..6143
        int P    = w >> 1;
        int r    = (w & 1) ? (NP - 1) : 0;
        int F    = (P >> 7) % 12;
        int ty   = F >> 2;

        long inb = (long)P * PLANE_IN;
        float* outrow = y + (long)P * PLANE_OUT + r * NP;

        if (r == 0) {
            int tbase = (NBT[F][0] - F) * FACE_DELTA;
            #pragma unroll
            for (int j = lane; j < NP; j += 32) {
                float v;
                if (j == 0) {
                    if (ty == 0) {
                        v = x[inb + (NBT[F][1] - F) * FACE_DELTA];              // tl[0,0]
                    } else if (ty == 1) {
                        int lb = (NBT[F][2] - F) * FACE_DELTA;
                        v = 0.5f * x[inb + tbase + (NN - 1) * NN]               // t[127,0]
                          + 0.5f * x[inb + lb + (NN - 1)];                      // lft[0,127]
                    } else {
                        v = x[inb + (NBT[F][1] - F) * FACE_DELTA
                              + (NN - 1) * NN + (NN - 1)];                      // tl[127,127]
                    }
                } else if (j == NP - 1) {
                    v = x[inb + (NBT[F][7] - F) * FACE_DELTA + (NN - 1) * NN];  // tr[127,0]
                } else {
                    int jj = j - 1;
                    v = (ty == 0) ? x[inb + tbase + jj * NN]                    // t[jj,0]
                                  : x[inb + tbase + (NN - 1) * NN + jj];        // t[127,jj]
                }
                outrow[j] = v;
            }
        } else {
            int bbase = (NBT[F][4] - F) * FACE_DELTA;
            #pragma unroll
            for (int j = lane; j < NP; j += 32) {
                float v;
                if (j == 0) {
                    v = x[inb + (NBT[F][3] - F) * FACE_DELTA + (NN - 1)];       // bl[0,127]
                } else if (j == NP - 1) {
                    if (ty == 0) {
                        v = x[inb + (NBT[F][5] - F) * FACE_DELTA];              // br[0,0]
                    } else if (ty == 1) {
                        int rb = (NBT[F][6] - F) * FACE_DELTA;
                        v = 0.5f * x[inb + bbase + (NN - 1)]                    // b[0,127]
                          + 0.5f * x[inb + rb + (NN - 1) * NN];                 // rgt[127,0]
                    } else {
                        v = x[inb + (NBT[F][5] - F) * FACE_DELTA
                              + (NN - 1) * NN + (NN - 1)];                      // br[127,127]
                    }
                } else {
                    int jj = j - 1;
                    v = (ty == 2) ? x[inb + bbase + jj * NN + (NN - 1)]         // b[jj,127]
                                  : x[inb + bbase + jj];                        // b[0,jj]
                }
                outrow[j] = v;
            }
        }
    }
}

extern "C" void kernel_launch(void* const* d_in, const int* in_sizes, int n_in,
                              void* d_out, int out_size)
{
    const float* x = (const float*)d_in[0];
    float* y = (float*)d_out;
    healpix_pad_kernel<<<TOTAL_BLOCKS, 256>>>(x, y);
}

// round 9
// speedup vs baseline: 1.2707x; 1.0030x over previous
#include <cuda_runtime.h>

// HEALPix p=1 padding: x (24,128,128,128) f32 -> y (24,128,130,130) f32
// One launch. Blocks [0,768) = halo rows; blocks [768,3840) = interior,
// one plane per block, 8 warps x 16 rows, 8-deep load->store pipeline
// with the prologue loads hoisted above the edge-staging barrier.

#define NN 128
#define NP 130
#define PLANE_IN  (NN*NN)          // 16384
#define PLANE_OUT (NP*NP)          // 16900
#define FACE_DELTA (128*PLANE_IN)  // 2097152
#define NPLANES 3072
#define HALO_BLOCKS ((NPLANES*2)/8)   // 768
#define TOTAL_BLOCKS (HALO_BLOCKS + NPLANES)

// Per-face neighbor table: t, tl, lft, bl, b, br, rgt, tr
__constant__ int NBT[12][8] = {
    {1, 2, 3, 3, 4, 8, 5, 1},      // F0  north
    {2, 3, 0, 0, 5, 9, 6, 2},      // F1
    {3, 0, 1, 1, 6, 10, 7, 3},     // F2
    {0, 1, 2, 2, 7, 11, 4, 0},     // F3
    {0, -1, 3, 7, 11, -1, 8, 5},   // F4  equatorial
    {1, -1, 0, 4, 8, -1, 9, 6},    // F5
    {2, -1, 1, 5, 9, -1, 10, 7},   // F6
    {3, -1, 2, 6, 10, -1, 11, 4},  // F7
    {5, 0, 4, 11, 11, 10, 9, 9},   // F8  south
    {6, 1, 5, 8, 8, 11, 10, 10},   // F9
    {7, 2, 6, 9, 9, 8, 11, 11},    // F10
    {4, 3, 7, 10, 10, 9, 8, 8},    // F11
};

__device__ __forceinline__ void store_row(
    float* __restrict__ outrow, float4 f4, float lh, float rh, int r, int lane)
{
    if (r & 1) {
        // odd r: aligned 16B chunks at cols [4k+2 .. 4k+5]
        float s = __shfl_down_sync(0xffffffffu, f4.x, 1);   // in[4*lane+4]
        if (lane == 31) s = rh;
        *reinterpret_cast<float4*>(outrow + 4 * lane + 2) =
            make_float4(f4.y, f4.z, f4.w, s);
        if (lane == 0) { outrow[0] = lh; outrow[1] = f4.x; }
    } else {
        // even r: aligned 16B chunks at cols [4k .. 4k+3]
        float s = __shfl_up_sync(0xffffffffu, f4.w, 1);     // in[4*lane-1]
        if (lane == 0) s = lh;
        *reinterpret_cast<float4*>(outrow + 4 * lane) =
            make_float4(s, f4.x, f4.y, f4.z);
        if (lane == 31) { outrow[128] = f4.w; outrow[129] = rh; }
    }
}

__global__ void __launch_bounds__(256) healpix_pad_kernel(
    const float* __restrict__ x, float* __restrict__ y)
{
    if (blockIdx.x >= HALO_BLOCKS) {
        // ================= interior rows: one plane per block =================
        __shared__ float sl[NN];   // left edge value per input row
        __shared__ float sr[NN];   // right edge value per input row

        int P    = blockIdx.x - HALO_BLOCKS;
        int tid  = threadIdx.x;
        int warp = tid >> 5;
        int lane = tid & 31;
        int F    = (P >> 7) % 12;
        int ty   = F >> 2;         // 0=north, 1=equatorial, 2=south

        const float* __restrict__ xin = x + (long)P * PLANE_IN;
        float* __restrict__ yout      = y + (long)P * PLANE_OUT;

        int lft_b = (NBT[F][2] - F) * FACE_DELTA;
        int rgt_b = (NBT[F][6] - F) * FACE_DELTA;

        int ir0 = warp * 16;
        const float* base = xin + ir0 * NN + 4 * lane;

        // 8-deep register FIFO prologue — independent of the edge staging,
        // issued BEFORE the barrier so the DRAM latency overlaps it.
        float4 buf[8];
        #pragma unroll
        for (int j = 0; j < 8; ++j)
            buf[j] = *reinterpret_cast<const float4*>(base + j * NN);

        // stage edge columns: 128 threads each side, all loads in flight
        if (tid < NN) {
            int ir = tid;
            sl[ir] = xin[(ty == 0) ? (lft_b + ir) : (lft_b + ir * NN + (NN - 1))];
        } else {
            int ir = tid - NN;
            sr[ir] = xin[(ty == 2) ? (rgt_b + (NN - 1) * NN + ir) : (rgt_b + ir * NN)];
        }
        __syncthreads();

        #pragma unroll
        for (int k = 0; k < 16; ++k) {
            float4 cur = buf[k & 7];
            if (k + 8 < 16)
                buf[k & 7] = *reinterpret_cast<const float4*>(base + (k + 8) * NN);
            int ir = ir0 + k;
            int r  = ir + 1;
            store_row(yout + r * NP, cur, sl[ir], sr[ir], r, lane);
        }
    } else {
        // ================= halo rows: 1 warp per row (runs first) =================
        int hb   = blockIdx.x;
        int warp = threadIdx.x >> 5;
        int lane = threadIdx.x & 31;
        int w    = hb * 8 + warp;              // 0..6143
        int P    = w >> 1;
        int r    = (w & 1) ? (NP - 1) : 0;
        int F    = (P >> 7) % 12;
        int ty   = F >> 2;

        long inb = (long)P * PLANE_IN;
        float* outrow = y + (long)P * PLANE_OUT + r * NP;

        if (r == 0) {
            int tbase = (NBT[F][0] - F) * FACE_DELTA;
            #pragma unroll
            for (int j = lane; j < NP; j += 32) {
                float v;
                if (j == 0) {
                    if (ty == 0) {
                        v = x[inb + (NBT[F][1] - F) * FACE_DELTA];              // tl[0,0]
                    } else if (ty == 1) {
                        int lb = (NBT[F][2] - F) * FACE_DELTA;
                        v = 0.5f * x[inb + tbase + (NN - 1) * NN]               // t[127,0]
                          + 0.5f * x[inb + lb + (NN - 1)];                      // lft[0,127]
                    } else {
                        v = x[inb + (NBT[F][1] - F) * FACE_DELTA
                              + (NN - 1) * NN + (NN - 1)];                      // tl[127,127]
                    }
                } else if (j == NP - 1) {
                    v = x[inb + (NBT[F][7] - F) * FACE_DELTA + (NN - 1) * NN];  // tr[127,0]
                } else {
                    int jj = j - 1;
                    v = (ty == 0) ? x[inb + tbase + jj * NN]                    // t[jj,0]
                                  : x[inb + tbase + (NN - 1) * NN + jj];        // t[127,jj]
                }
                outrow[j] = v;
            }
        } else {
            int bbase = (NBT[F][4] - F) * FACE_DELTA;
            #pragma unroll
            for (int j = lane; j < NP; j += 32) {
                float v;
                if (j == 0) {
                    v = x[inb + (NBT[F][3] - F) * FACE_DELTA + (NN - 1)];       // bl[0,127]
                } else if (j == NP - 1) {
                    if (ty == 0) {
                        v = x[inb + (NBT[F][5] - F) * FACE_DELTA];              // br[0,0]
                    } else if (ty == 1) {
                        int rb = (NBT[F][6] - F) * FACE_DELTA;
                        v = 0.5f * x[inb + bbase + (NN - 1)]                    // b[0,127]
                          + 0.5f * x[inb + rb + (NN - 1) * NN];                 // rgt[127,0]
                    } else {
                        v = x[inb + (NBT[F][5] - F) * FACE_DELTA
                              + (NN - 1) * NN + (NN - 1)];                      // br[127,127]
                    }
                } else {
                    int jj = j - 1;
                    v = (ty == 2) ? x[inb + bbase + jj * NN + (NN - 1)]         // b[jj,127]
                                  : x[inb + bbase + jj];                        // b[0,jj]
                }
                outrow[j] = v;
            }
        }
    }
}

extern "C" void kernel_launch(void* const* d_in, const int* in_sizes, int n_in,
                              void* d_out, int out_size)
{
    const float* x = (const float*)d_in[0];
    float* y = (float*)d_out;
    healpix_pad_kernel<<<TOTAL_BLOCKS, 256>>>(x, y);
}

// round 10
// speedup vs baseline: 1.2745x; 1.0030x over previous
#include <cuda_runtime.h>

// HEALPix p=1 padding: x (24,128,128,128) f32 -> y (24,128,130,130) f32
// One launch. Blocks [0,768) = halo rows; blocks [768,3840) = interior,
// one plane per block, 8 warps x 16 rows. Full phase separation:
// each warp loads ALL 16 of its rows into registers (pure read burst),
// then stores all 16 (pure write burst) — maximal same-direction DRAM runs.

#define NN 128
#define NP 130
#define PLANE_IN  (NN*NN)          // 16384
#define PLANE_OUT (NP*NP)          // 16900
#define FACE_DELTA (128*PLANE_IN)  // 2097152
#define NPLANES 3072
#define HALO_BLOCKS ((NPLANES*2)/8)   // 768
#define TOTAL_BLOCKS (HALO_BLOCKS + NPLANES)

// Per-face neighbor table: t, tl, lft, bl, b, br, rgt, tr
__constant__ int NBT[12][8] = {
    {1, 2, 3, 3, 4, 8, 5, 1},      // F0  north
    {2, 3, 0, 0, 5, 9, 6, 2},      // F1
    {3, 0, 1, 1, 6, 10, 7, 3},     // F2
    {0, 1, 2, 2, 7, 11, 4, 0},     // F3
    {0, -1, 3, 7, 11, -1, 8, 5},   // F4  equatorial
    {1, -1, 0, 4, 8, -1, 9, 6},    // F5
    {2, -1, 1, 5, 9, -1, 10, 7},   // F6
    {3, -1, 2, 6, 10, -1, 11, 4},  // F7
    {5, 0, 4, 11, 11, 10, 9, 9},   // F8  south
    {6, 1, 5, 8, 8, 11, 10, 10},   // F9
    {7, 2, 6, 9, 9, 8, 11, 11},    // F10
    {4, 3, 7, 10, 10, 9, 8, 8},    // F11
};

__device__ __forceinline__ void store_row(
    float* __restrict__ outrow, float4 f4, float lh, float rh, int r, int lane)
{
    if (r & 1) {
        // odd r: aligned 16B chunks at cols [4k+2 .. 4k+5]
        float s = __shfl_down_sync(0xffffffffu, f4.x, 1);   // in[4*lane+4]
        if (lane == 31) s = rh;
        *reinterpret_cast<float4*>(outrow + 4 * lane + 2) =
            make_float4(f4.y, f4.z, f4.w, s);
        if (lane == 0) { outrow[0] = lh; outrow[1] = f4.x; }
    } else {
        // even r: aligned 16B chunks at cols [4k .. 4k+3]
        float s = __shfl_up_sync(0xffffffffu, f4.w, 1);     // in[4*lane-1]
        if (lane == 0) s = lh;
        *reinterpret_cast<float4*>(outrow + 4 * lane) =
            make_float4(s, f4.x, f4.y, f4.z);
        if (lane == 31) { outrow[128] = f4.w; outrow[129] = rh; }
    }
}

__global__ void __launch_bounds__(256) healpix_pad_kernel(
    const float* __restrict__ x, float* __restrict__ y)
{
    if (blockIdx.x >= HALO_BLOCKS) {
        // ================= interior rows: one plane per block =================
        __shared__ float sl[NN];   // left edge value per input row
        __shared__ float sr[NN];   // right edge value per input row

        int P    = blockIdx.x - HALO_BLOCKS;
        int tid  = threadIdx.x;
        int warp = tid >> 5;
        int lane = tid & 31;
        int F    = (P >> 7) % 12;
        int ty   = F >> 2;         // 0=north, 1=equatorial, 2=south

        const float* __restrict__ xin = x + (long)P * PLANE_IN;
        float* __restrict__ yout      = y + (long)P * PLANE_OUT;

        int lft_b = (NBT[F][2] - F) * FACE_DELTA;
        int rgt_b = (NBT[F][6] - F) * FACE_DELTA;

        int ir0 = warp * 16;
        const float* base = xin + ir0 * NN + 4 * lane;

        // Phase 1: pure read burst — all 16 rows into registers, issued
        // before the barrier so the DRAM latency overlaps edge staging.
        float4 buf[16];
        #pragma unroll
        for (int j = 0; j < 16; ++j)
            buf[j] = *reinterpret_cast<const float4*>(base + j * NN);

        // stage edge columns: 128 threads each side, all loads in flight
        if (tid < NN) {
            int ir = tid;
            sl[ir] = xin[(ty == 0) ? (lft_b + ir) : (lft_b + ir * NN + (NN - 1))];
        } else {
            int ir = tid - NN;
            sr[ir] = xin[(ty == 2) ? (rgt_b + (NN - 1) * NN + ir) : (rgt_b + ir * NN)];
        }
        __syncthreads();

        // Phase 2: pure write burst — all 16 rows out.
        #pragma unroll
        for (int k = 0; k < 16; ++k) {
            int ir = ir0 + k;
            int r  = ir + 1;
            store_row(yout + r * NP, buf[k], sl[ir], sr[ir], r, lane);
        }
    } else {
        // ================= halo rows: 1 warp per row (runs first) =================
        int hb   = blockIdx.x;
        int warp = threadIdx.x >> 5;
        int lane = threadIdx.x & 31;
        int w    = hb * 8 + warp;              // 0..6143
        int P    = w >> 1;
        int r    = (w & 1) ? (NP - 1) : 0;
        int F    = (P >> 7) % 12;
        int ty   = F >> 2;

        long inb = (long)P * PLANE_IN;
        float* outrow = y + (long)P * PLANE_OUT + r * NP;

        if (r == 0) {
            int tbase = (NBT[F][0] - F) * FACE_DELTA;
            #pragma unroll
            for (int j = lane; j < NP; j += 32) {
                float v;
                if (j == 0) {
                    if (ty == 0) {
                        v = x[inb + (NBT[F][1] - F) * FACE_DELTA];              // tl[0,0]
                    } else if (ty == 1) {
                        int lb = (NBT[F][2] - F) * FACE_DELTA;
                        v = 0.5f * x[inb + tbase + (NN - 1) * NN]               // t[127,0]
                          + 0.5f * x[inb + lb + (NN - 1)];                      // lft[0,127]
                    } else {
                        v = x[inb + (NBT[F][1] - F) * FACE_DELTA
                              + (NN - 1) * NN + (NN - 1)];                      // tl[127,127]
                    }
                } else if (j == NP - 1) {
                    v = x[inb + (NBT[F][7] - F) * FACE_DELTA + (NN - 1) * NN];  // tr[127,0]
                } else {
                    int jj = j - 1;
                    v = (ty == 0) ? x[inb + tbase + jj * NN]                    // t[jj,0]
                                  : x[inb + tbase + (NN - 1) * NN + jj];        // t[127,jj]
                }
                outrow[j] = v;
            }
        } else {
            int bbase = (NBT[F][4] - F) * FACE_DELTA;
            #pragma unroll
            for (int j = lane; j < NP; j += 32) {
                float v;
                if (j == 0) {
                    v = x[inb + (NBT[F][3] - F) * FACE_DELTA + (NN - 1)];       // bl[0,127]
                } else if (j == NP - 1) {
                    if (ty == 0) {
                        v = x[inb + (NBT[F][5] - F) * FACE_DELTA];              // br[0,0]
                    } else if (ty == 1) {
                        int rb = (NBT[F][6] - F) * FACE_DELTA;
                        v = 0.5f * x[inb + bbase + (NN - 1)]                    // b[0,127]
                          + 0.5f * x[inb + rb + (NN - 1) * NN];                 // rgt[127,0]
                    } else {
                        v = x[inb + (NBT[F][5] - F) * FACE_DELTA
                              + (NN - 1) * NN + (NN - 1)];                      // br[127,127]
                    }
                } else {
                    int jj = j - 1;
                    v = (ty == 2) ? x[inb + bbase + jj * NN + (NN - 1)]         // b[jj,127]
                                  : x[inb + bbase + jj];                        // b[0,jj]
                }
                outrow[j] = v;
            }
        }
    }
}

extern "C" void kernel_launch(void* const* d_in, const int* in_sizes, int n_in,
                              void* d_out, int out_size)
{
    const float* x = (const float*)d_in[0];
    float* y = (float*)d_out;
    healpix_pad_kernel<<<TOTAL_BLOCKS, 256>>>(x, y);
}

// round 12
// speedup vs baseline: 1.3067x; 1.0253x over previous
#include <cuda_runtime.h>

// HEALPix p=1 padding: x (24,128,128,128) f32 -> y (24,128,130,130) f32
// One launch. Blocks [0,768) = halo rows; blocks [768,3840) = interior.
// Interior blocks are CHANNEL-MAJOR remapped: 12 consecutive blocks handle
// the 12 faces of one (batch,channel), so neighbor-edge gathers hit L2 lines
// that sibling blocks in the same wave are streaming anyway.
// Per block: one plane, 8 warps x 16 rows, 8-deep load->store FIFO with the
// prologue hoisted above the edge-staging barrier.

#define NN 128
#define NP 130
#define PLANE_IN  (NN*NN)          // 16384
#define PLANE_OUT (NP*NP)          // 16900
#define FACE_DELTA (128*PLANE_IN)  // 2097152
#define NPLANES 3072
#define HALO_BLOCKS ((NPLANES*2)/8)   // 768
#define TOTAL_BLOCKS (HALO_BLOCKS + NPLANES)

// Per-face neighbor table: t, tl, lft, bl, b, br, rgt, tr
__constant__ int NBT[12][8] = {
    {1, 2, 3, 3, 4, 8, 5, 1},      // F0  north
    {2, 3, 0, 0, 5, 9, 6, 2},      // F1
    {3, 0, 1, 1, 6, 10, 7, 3},     // F2
    {0, 1, 2, 2, 7, 11, 4, 0},     // F3
    {0, -1, 3, 7, 11, -1, 8, 5},   // F4  equatorial
    {1, -1, 0, 4, 8, -1, 9, 6},    // F5
    {2, -1, 1, 5, 9, -1, 10, 7},   // F6
    {3, -1, 2, 6, 10, -1, 11, 4},  // F7
    {5, 0, 4, 11, 11, 10, 9, 9},   // F8  south
    {6, 1, 5, 8, 8, 11, 10, 10},   // F9
    {7, 2, 6, 9, 9, 8, 11, 11},    // F10
    {4, 3, 7, 10, 10, 9, 8, 8},    // F11
};

__device__ __forceinline__ void store_row(
    float* __restrict__ outrow, float4 f4, float lh, float rh, int r, int lane)
{
    if (r & 1) {
        // odd r: aligned 16B chunks at cols [4k+2 .. 4k+5]
        float s = __shfl_down_sync(0xffffffffu, f4.x, 1);   // in[4*lane+4]
        if (lane == 31) s = rh;
        *reinterpret_cast<float4*>(outrow + 4 * lane + 2) =
            make_float4(f4.y, f4.z, f4.w, s);
        if (lane == 0) { outrow[0] = lh; outrow[1] = f4.x; }
    } else {
        // even r: aligned 16B chunks at cols [4k .. 4k+3]
        float s = __shfl_up_sync(0xffffffffu, f4.w, 1);     // in[4*lane-1]
        if (lane == 0) s = lh;
        *reinterpret_cast<float4*>(outrow + 4 * lane) =
            make_float4(s, f4.x, f4.y, f4.z);
        if (lane == 31) { outrow[128] = f4.w; outrow[129] = rh; }
    }
}

__global__ void __launch_bounds__(256) healpix_pad_kernel(
    const float* __restrict__ x, float* __restrict__ y)
{
    if (blockIdx.x >= HALO_BLOCKS) {
        // ================= interior rows: one plane per block =================
        __shared__ float sl[NN];   // left edge value per input row
        __shared__ float sr[NN];   // right edge value per input row

        // channel-major remap: consecutive blocks = 12 faces of one (b,chan)
        int idx  = blockIdx.x - HALO_BLOCKS;      // 0..3071
        int F    = idx % 12;
        int g    = idx / 12;                      // 0..255 = (b, chan)
        int b2   = g >> 7;                        // batch pair index (0..1)
        int c    = g & 127;                       // channel
        int P    = (b2 * 12 + F) * 128 + c;

        int tid  = threadIdx.x;
        int warp = tid >> 5;
        int lane = tid & 31;
        int ty   = F >> 2;         // 0=north, 1=equatorial, 2=south

        const float* __restrict__ xin = x + (long)P * PLANE_IN;
        float* __restrict__ yout      = y + (long)P * PLANE_OUT;

        int lft_b = (NBT[F][2] - F) * FACE_DELTA;
        int rgt_b = (NBT[F][6] - F) * FACE_DELTA;

        int ir0 = warp * 16;
        const float* base = xin + ir0 * NN + 4 * lane;

        // 8-deep FIFO prologue — issued before the barrier
        float4 buf[8];
        #pragma unroll
        for (int j = 0; j < 8; ++j)
            buf[j] = *reinterpret_cast<const float4*>(base + j * NN);

        // stage edge columns: 128 threads each side, all loads in flight
        if (tid < NN) {
            int ir = tid;
            sl[ir] = xin[(ty == 0) ? (lft_b + ir) : (lft_b + ir * NN + (NN - 1))];
        } else {
            int ir = tid - NN;
            sr[ir] = xin[(ty == 2) ? (rgt_b + (NN - 1) * NN + ir) : (rgt_b + ir * NN)];
        }
        __syncthreads();

        #pragma unroll
        for (int k = 0; k < 16; ++k) {
            float4 cur = buf[k & 7];
            if (k + 8 < 16)
                buf[k & 7] = *reinterpret_cast<const float4*>(base + (k + 8) * NN);
            int ir = ir0 + k;
            int r  = ir + 1;
            store_row(yout + r * NP, cur, sl[ir], sr[ir], r, lane);
        }
    } else {
        // ================= halo rows: 1 warp per row (runs first) =================
        int hb   = blockIdx.x;
        int warp = threadIdx.x >> 5;
        int lane = threadIdx.x & 31;
        int w    = hb * 8 + warp;              // 0..6143
        int hidx = w >> 1;                     // 0..3071, channel-major remap too
        int F    = hidx % 12;
        int g    = hidx / 12;
        int P    = ((g >> 7) * 12 + F) * 128 + (g & 127);
        int r    = (w & 1) ? (NP - 1) : 0;
        int ty   = F >> 2;

        long inb = (long)P * PLANE_IN;
        float* outrow = y + (long)P * PLANE_OUT + r * NP;

        if (r == 0) {
            int tbase = (NBT[F][0] - F) * FACE_DELTA;
            #pragma unroll
            for (int j = lane; j < NP; j += 32) {
                float v;
                if (j == 0) {
                    if (ty == 0) {
                        v = x[inb + (NBT[F][1] - F) * FACE_DELTA];              // tl[0,0]
                    } else if (ty == 1) {
                        int lb = (NBT[F][2] - F) * FACE_DELTA;
                        v = 0.5f * x[inb + tbase + (NN - 1) * NN]               // t[127,0]
                          + 0.5f * x[inb + lb + (NN - 1)];                      // lft[0,127]
                    } else {
                        v = x[inb + (NBT[F][1] - F) * FACE_DELTA
                              + (NN - 1) * NN + (NN - 1)];                      // tl[127,127]
                    }
                } else if (j == NP - 1) {
                    v = x[inb + (NBT[F][7] - F) * FACE_DELTA + (NN - 1) * NN];  // tr[127,0]
                } else {
                    int jj = j - 1;
                    v = (ty == 0) ? x[inb + tbase + jj * NN]                    // t[jj,0]
                                  : x[inb + tbase + (NN - 1) * NN + jj];        // t[127,jj]
                }
                outrow[j] = v;
            }
        } else {
            int bbase = (NBT[F][4] - F) * FACE_DELTA;
            #pragma unroll
            for (int j = lane; j < NP; j += 32) {
                float v;
                if (j == 0) {
                    v = x[inb + (NBT[F][3] - F) * FACE_DELTA + (NN - 1)];       // bl[0,127]
                } else if (j == NP - 1) {
                    if (ty == 0) {
                        v = x[inb + (NBT[F][5] - F) * FACE_DELTA];              // br[0,0]
                    } else if (ty == 1) {
                        int rb = (NBT[F][6] - F) * FACE_DELTA;
                        v = 0.5f * x[inb + bbase + (NN - 1)]                    // b[0,127]
                          + 0.5f * x[inb + rb + (NN - 1) * NN];                 // rgt[127,0]
                    } else {
                        v = x[inb + (NBT[F][5] - F) * FACE_DELTA
                              + (NN - 1) * NN + (NN - 1)];                      // br[127,127]
                    }
                } else {
                    int jj = j - 1;
                    v = (ty == 2) ? x[inb + bbase + jj * NN + (NN - 1)]         // b[jj,127]
                                  : x[inb + bbase + jj];                        // b[0,jj]
                }
                outrow[j] = v;
            }
        }
    }
}

extern "C" void kernel_launch(void* const* d_in, const int* in_sizes, int n_in,
                              void* d_out, int out_size)
{
    const float* x = (const float*)d_in[0];
    float* y = (float*)d_out;
    healpix_pad_kernel<<<TOTAL_BLOCKS, 256>>>(x, y);
}

// round 13
// speedup vs baseline: 1.3126x; 1.0045x over previous
#include <cuda_runtime.h>

// HEALPix p=1 padding: x (24,128,128,128) f32 -> y (24,128,130,130) f32
// 3072 blocks, one plane each, channel-major remapped (12 consecutive blocks
// = the 12 faces of one (batch,channel) so cross-face gathers hit L2).
// Each block: 8 warps x 16 interior rows (8-deep load->store FIFO, prologue
// hoisted above the edge-staging barrier), then warps 0-3 emit the top halo
// row and warps 4-7 the bottom halo row (fused, no separate blocks).

#define NN 128
#define NP 130
#define PLANE_IN  (NN*NN)          // 16384
#define PLANE_OUT (NP*NP)          // 16900
#define FACE_DELTA (128*PLANE_IN)  // 2097152
#define NPLANES 3072

// Per-face neighbor table: t, tl, lft, bl, b, br, rgt, tr
__constant__ int NBT[12][8] = {
    {1, 2, 3, 3, 4, 8, 5, 1},      // F0  north
    {2, 3, 0, 0, 5, 9, 6, 2},      // F1
    {3, 0, 1, 1, 6, 10, 7, 3},     // F2
    {0, 1, 2, 2, 7, 11, 4, 0},     // F3
    {0, -1, 3, 7, 11, -1, 8, 5},   // F4  equatorial
    {1, -1, 0, 4, 8, -1, 9, 6},    // F5
    {2, -1, 1, 5, 9, -1, 10, 7},   // F6
    {3, -1, 2, 6, 10, -1, 11, 4},  // F7
    {5, 0, 4, 11, 11, 10, 9, 9},   // F8  south
    {6, 1, 5, 8, 8, 11, 10, 10},   // F9
    {7, 2, 6, 9, 9, 8, 11, 11},    // F10
    {4, 3, 7, 10, 10, 9, 8, 8},    // F11
};

__device__ __forceinline__ void store_row(
    float* __restrict__ outrow, float4 f4, float lh, float rh, int r, int lane)
{
    if (r & 1) {
        // odd r: aligned 16B chunks at cols [4k+2 .. 4k+5]
        float s = __shfl_down_sync(0xffffffffu, f4.x, 1);   // in[4*lane+4]
        if (lane == 31) s = rh;
        *reinterpret_cast<float4*>(outrow + 4 * lane + 2) =
            make_float4(f4.y, f4.z, f4.w, s);
        if (lane == 0) { outrow[0] = lh; outrow[1] = f4.x; }
    } else {
        // even r: aligned 16B chunks at cols [4k .. 4k+3]
        float s = __shfl_up_sync(0xffffffffu, f4.w, 1);     // in[4*lane-1]
        if (lane == 0) s = lh;
        *reinterpret_cast<float4*>(outrow + 4 * lane) =
            make_float4(s, f4.x, f4.y, f4.z);
        if (lane == 31) { outrow[128] = f4.w; outrow[129] = rh; }
    }
}

// value of the top halo row (output row 0) at column j, for plane base xin
__device__ __forceinline__ float top_halo_val(
    const float* __restrict__ xin, int F, int ty, int j)
{
    int tbase = (NBT[F][0] - F) * FACE_DELTA;
    if (j == 0) {
        if (ty == 0)
            return xin[(NBT[F][1] - F) * FACE_DELTA];                    // tl[0,0]
        if (ty == 1) {
            int lb = (NBT[F][2] - F) * FACE_DELTA;
            return 0.5f * xin[tbase + (NN - 1) * NN]                     // t[127,0]
                 + 0.5f * xin[lb + (NN - 1)];                            // lft[0,127]
        }
        return xin[(NBT[F][1] - F) * FACE_DELTA + (NN - 1) * NN + (NN - 1)]; // tl[127,127]
    }
    if (j == NP - 1)
        return xin[(NBT[F][7] - F) * FACE_DELTA + (NN - 1) * NN];        // tr[127,0]
    int jj = j - 1;
    return (ty == 0) ? xin[tbase + jj * NN]                              // t[jj,0]
                     : xin[tbase + (NN - 1) * NN + jj];                  // t[127,jj]
}

// value of the bottom halo row (output row 129) at column j
__device__ __forceinline__ float bot_halo_val(
    const float* __restrict__ xin, int F, int ty, int j)
{
    int bbase = (NBT[F][4] - F) * FACE_DELTA;
    if (j == 0)
        return xin[(NBT[F][3] - F) * FACE_DELTA + (NN - 1)];             // bl[0,127]
    if (j == NP - 1) {
        if (ty == 0)
            return xin[(NBT[F][5] - F) * FACE_DELTA];                    // br[0,0]
        if (ty == 1) {
            int rb = (NBT[F][6] - F) * FACE_DELTA;
            return 0.5f * xin[bbase + (NN - 1)]                          // b[0,127]
                 + 0.5f * xin[rb + (NN - 1) * NN];                       // rgt[127,0]
        }
        return xin[(NBT[F][5] - F) * FACE_DELTA + (NN - 1) * NN + (NN - 1)]; // br[127,127]
    }
    int jj = j - 1;
    return (ty == 2) ? xin[bbase + jj * NN + (NN - 1)]                   // b[jj,127]
                     : xin[bbase + jj];                                  // b[0,jj]
}

__global__ void __launch_bounds__(256) healpix_pad_kernel(
    const float* __restrict__ x, float* __restrict__ y)
{
    __shared__ float sl[NN];   // left edge value per input row
    __shared__ float sr[NN];   // right edge value per input row

    // channel-major remap: consecutive blocks = 12 faces of one (b,chan)
    int idx  = blockIdx.x;                    // 0..3071
    int F    = idx % 12;
    int g    = idx / 12;                      // 0..255 = (b2, chan)
    int P    = ((g >> 7) * 12 + F) * 128 + (g & 127);

    int tid  = threadIdx.x;
    int warp = tid >> 5;
    int lane = tid & 31;
    int ty   = F >> 2;         // 0=north, 1=equatorial, 2=south

    const float* __restrict__ xin = x + (long)P * PLANE_IN;
    float* __restrict__ yout      = y + (long)P * PLANE_OUT;

    int lft_b = (NBT[F][2] - F) * FACE_DELTA;
    int rgt_b = (NBT[F][6] - F) * FACE_DELTA;

    int ir0 = warp * 16;
    const float* base = xin + ir0 * NN + 4 * lane;

    // 8-deep FIFO prologue — issued before the barrier
    float4 buf[8];
    #pragma unroll
    for (int j = 0; j < 8; ++j)
        buf[j] = *reinterpret_cast<const float4*>(base + j * NN);

    // stage edge columns: 128 threads each side, all loads in flight
    if (tid < NN) {
        int ir = tid;
        sl[ir] = xin[(ty == 0) ? (lft_b + ir) : (lft_b + ir * NN + (NN - 1))];
    } else {
        int ir = tid - NN;
        sr[ir] = xin[(ty == 2) ? (rgt_b + (NN - 1) * NN + ir) : (rgt_b + ir * NN)];
    }
    __syncthreads();

    #pragma unroll
    for (int k = 0; k < 16; ++k) {
        float4 cur = buf[k & 7];
        if (k + 8 < 16)
            buf[k & 7] = *reinterpret_cast<const float4*>(base + (k + 8) * NN);
        int ir = ir0 + k;
        int r  = ir + 1;
        store_row(yout + r * NP, cur, sl[ir], sr[ir], r, lane);
    }

    // -------- fused halo rows: warps 0-3 top (r=0), warps 4-7 bottom (r=129) ----
    {
        int j0 = (warp & 3) * 32 + lane;      // 0..127; +128 covers 128,129
        if (warp < 4) {
            float* outrow = yout;             // r = 0
            for (int j = j0; j < NP; j += 128)
                outrow[j] = top_halo_val(xin, F, ty, j);
        } else {
            float* outrow = yout + (NP - 1) * NP;   // r = 129
            for (int j = j0; j < NP; j += 128)
                outrow[j] = bot_halo_val(xin, F, ty, j);
        }
    }
}

extern "C" void kernel_launch(void* const* d_in, const int* in_sizes, int n_in,
                              void* d_out, int out_size)
{
    const float* x = (const float*)d_in[0];
    float* y = (float*)d_out;
    healpix_pad_kernel<<<NPLANES, 256>>>(x, y);
}

// round 14
// speedup vs baseline: 1.3958x; 1.0634x over previous
#include <cuda_runtime.h>

// HEALPix p=1 padding: x (24,128,128,128) f32 -> y (24,128,130,130) f32
// 3072 blocks, one plane each, channel-major remapped (12 consecutive blocks
// = the 12 faces of one (batch,channel) so cross-face gathers hit L2).
// Each block: halo-row values gathered into registers EARLY (latency overlaps
// the interior stream), 8 warps x 16 interior rows (8-deep load->store FIFO,
// prologue hoisted above the edge-staging barrier), halo stores at the end.

#define NN 128
#define NP 130
#define PLANE_IN  (NN*NN)          // 16384
#define PLANE_OUT (NP*NP)          // 16900
#define FACE_DELTA (128*PLANE_IN)  // 2097152
#define NPLANES 3072

// Per-face neighbor table: t, tl, lft, bl, b, br, rgt, tr
__constant__ int NBT[12][8] = {
    {1, 2, 3, 3, 4, 8, 5, 1},      // F0  north
    {2, 3, 0, 0, 5, 9, 6, 2},      // F1
    {3, 0, 1, 1, 6, 10, 7, 3},     // F2
    {0, 1, 2, 2, 7, 11, 4, 0},     // F3
    {0, -1, 3, 7, 11, -1, 8, 5},   // F4  equatorial
    {1, -1, 0, 4, 8, -1, 9, 6},    // F5
    {2, -1, 1, 5, 9, -1, 10, 7},   // F6
    {3, -1, 2, 6, 10, -1, 11, 4},  // F7
    {5, 0, 4, 11, 11, 10, 9, 9},   // F8  south
    {6, 1, 5, 8, 8, 11, 10, 10},   // F9
    {7, 2, 6, 9, 9, 8, 11, 11},    // F10
    {4, 3, 7, 10, 10, 9, 8, 8},    // F11
};

__device__ __forceinline__ void store_row(
    float* __restrict__ outrow, float4 f4, float lh, float rh, int r, int lane)
{
    if (r & 1) {
        // odd r: aligned 16B chunks at cols [4k+2 .. 4k+5]
        float s = __shfl_down_sync(0xffffffffu, f4.x, 1);   // in[4*lane+4]
        if (lane == 31) s = rh;
        *reinterpret_cast<float4*>(outrow + 4 * lane + 2) =
            make_float4(f4.y, f4.z, f4.w, s);
        if (lane == 0) { outrow[0] = lh; outrow[1] = f4.x; }
    } else {
        // even r: aligned 16B chunks at cols [4k .. 4k+3]
        float s = __shfl_up_sync(0xffffffffu, f4.w, 1);     // in[4*lane-1]
        if (lane == 0) s = lh;
        *reinterpret_cast<float4*>(outrow + 4 * lane) =
            make_float4(s, f4.x, f4.y, f4.z);
        if (lane == 31) { outrow[128] = f4.w; outrow[129] = rh; }
    }
}

// value of the top halo row (output row 0) at column j, for plane base xin
__device__ __forceinline__ float top_halo_val(
    const float* __restrict__ xin, int F, int ty, int j)
{
    int tbase = (NBT[F][0] - F) * FACE_DELTA;
    if (j == 0) {
        if (ty == 0)
            return xin[(NBT[F][1] - F) * FACE_DELTA];                    // tl[0,0]
        if (ty == 1) {
            int lb = (NBT[F][2] - F) * FACE_DELTA;
            return 0.5f * xin[tbase + (NN - 1) * NN]                     // t[127,0]
                 + 0.5f * xin[lb + (NN - 1)];                            // lft[0,127]
        }
        return xin[(NBT[F][1] - F) * FACE_DELTA + (NN - 1) * NN + (NN - 1)]; // tl[127,127]
    }
    if (j == NP - 1)
        return xin[(NBT[F][7] - F) * FACE_DELTA + (NN - 1) * NN];        // tr[127,0]
    int jj = j - 1;
    return (ty == 0) ? xin[tbase + jj * NN]                              // t[jj,0]
                     : xin[tbase + (NN - 1) * NN + jj];                  // t[127,jj]
}

// value of the bottom halo row (output row 129) at column j
__device__ __forceinline__ float bot_halo_val(
    const float* __restrict__ xin, int F, int ty, int j)
{
    int bbase = (NBT[F][4] - F) * FACE_DELTA;
    if (j == 0)
        return xin[(NBT[F][3] - F) * FACE_DELTA + (NN - 1)];             // bl[0,127]
    if (j == NP - 1) {
        if (ty == 0)
            return xin[(NBT[F][5] - F) * FACE_DELTA];                    // br[0,0]
        if (ty == 1) {
            int rb = (NBT[F][6] - F) * FACE_DELTA;
            return 0.5f * xin[bbase + (NN - 1)]                          // b[0,127]
                 + 0.5f * xin[rb + (NN - 1) * NN];                       // rgt[127,0]
        }
        return xin[(NBT[F][5] - F) * FACE_DELTA + (NN - 1) * NN + (NN - 1)]; // br[127,127]
    }
    int jj = j - 1;
    return (ty == 2) ? xin[bbase + jj * NN + (NN - 1)]                   // b[jj,127]
                     : xin[bbase + jj];                                  // b[0,jj]
}

__global__ void __launch_bounds__(256) healpix_pad_kernel(
    const float* __restrict__ x, float* __restrict__ y)
{
    __shared__ float sl[NN];   // left edge value per input row
    __shared__ float sr[NN];   // right edge value per input row

    // channel-major remap: consecutive blocks = 12 faces of one (b,chan)
    int idx  = blockIdx.x;                    // 0..3071
    int F    = idx % 12;
    int g    = idx / 12;                      // 0..255 = (b2, chan)
    int P    = ((g >> 7) * 12 + F) * 128 + (g & 127);

    int tid  = threadIdx.x;
    int warp = tid >> 5;
    int lane = tid & 31;
    int ty   = F >> 2;         // 0=north, 1=equatorial, 2=south

    const float* __restrict__ xin = x + (long)P * PLANE_IN;
    float* __restrict__ yout      = y + (long)P * PLANE_OUT;

    int lft_b = (NBT[F][2] - F) * FACE_DELTA;
    int rgt_b = (NBT[F][6] - F) * FACE_DELTA;

    int ir0 = warp * 16;
    const float* base = xin + ir0 * NN + 4 * lane;

    // 8-deep FIFO prologue — issued before the barrier
    float4 buf[8];
    #pragma unroll
    for (int j = 0; j < 8; ++j)
        buf[j] = *reinterpret_cast<const float4*>(base + j * NN);

    // stage edge columns: 128 threads each side, all loads in flight
    if (tid < NN) {
        int ir = tid;
        sl[ir] = xin[(ty == 0) ? (lft_b + ir) : (lft_b + ir * NN + (NN - 1))];
    } else {
        int ir = tid - NN;
        sr[ir] = xin[(ty == 2) ? (rgt_b + (NN - 1) * NN + ir) : (rgt_b + ir * NN)];
    }

    // -------- halo gathers hoisted: loads issued here, stores at the end ----
    int j0 = (warp & 3) * 32 + lane;          // 0..127 (j0<2 also covers 128,129)
    float hv0, hv1 = 0.0f;
    if (warp < 4) {
        hv0 = top_halo_val(xin, F, ty, j0);
        if (j0 < 2) hv1 = top_halo_val(xin, F, ty, j0 + 128);
    } else {
        hv0 = bot_halo_val(xin, F, ty, j0);
        if (j0 < 2) hv1 = bot_halo_val(xin, F, ty, j0 + 128);
    }
    __syncthreads();

    #pragma unroll
    for (int k = 0; k < 16; ++k) {
        float4 cur = buf[k & 7];
        if (k + 8 < 16)
            buf[k & 7] = *reinterpret_cast<const float4*>(base + (k + 8) * NN);
        int ir = ir0 + k;
        int r  = ir + 1;
        store_row(yout + r * NP, cur, sl[ir], sr[ir], r, lane);
    }

    // -------- halo stores (values already resident in registers) ----
    {
        float* outrow = (warp < 4) ? yout : (yout + (NP - 1) * NP);
        outrow[j0] = hv0;
        if (j0 < 2) outrow[j0 + 128] = hv1;
    }
}

extern "C" void kernel_launch(void* const* d_in, const int* in_sizes, int n_in,
                              void* d_out, int out_size)
{
    const float* x = (const float*)d_in[0];
    float* y = (float*)d_out;
    healpix_pad_kernel<<<NPLANES, 256>>>(x, y);
}